// round 1
// baseline (speedup 1.0000x reference)
#include <cuda_runtime.h>
#include <cuda_bf16.h>

#define NMAX 50000

// ---------------- scratch (static __device__, no allocs) ----------------
__device__ float    g_h1[NMAX * 64];      // layer1 features x@W1
__device__ float    g_asrc1[NMAX * 8];
__device__ float    g_adst1[NMAX * 8];
__device__ unsigned g_max1[NMAX * 8];     // encoded float max
__device__ float    g_maxf1[NMAX * 8];    // decoded max
__device__ float    g_denom1[NMAX * 8];
__device__ float    g_acc1[NMAX * 64];
__device__ float    g_h2in[NMAX * 64];    // relu(layer1 out)
__device__ float    g_h2[NMAX * 40];      // h2in@W2
__device__ float    g_as2[NMAX];
__device__ float    g_ad2[NMAX];
__device__ unsigned g_max2[NMAX];
__device__ float    g_maxf2[NMAX];
__device__ float    g_denom2[NMAX];
__device__ float    g_acc2[NMAX * 40];

// ---------------- helpers ----------------
__device__ __forceinline__ float leaky(float e) { return e >= 0.f ? e : 0.2f * e; }

// order-preserving float<->uint for atomicMax
__device__ __forceinline__ unsigned fenc(float f) {
    unsigned u = __float_as_uint(f);
    return (u & 0x80000000u) ? ~u : (u | 0x80000000u);
}
__device__ __forceinline__ float fdec(unsigned u) {
    return __uint_as_float((u & 0x80000000u) ? (u & 0x7fffffffu) : ~u);
}

// ---------------- SGEMM: C[M,N] = A[M,K] @ B[K,N], BM=64 BN=64 BK=16 ----------------
// 256 threads, 4x4 microtile. Requires K % 16 == 0, N % 4 == 0 (true: K=512/64, N=64/40).
__global__ void sgemm64(const float* __restrict__ A, const float* __restrict__ B,
                        float* __restrict__ C, int M, int N, int K) {
    __shared__ float As[16][64];   // [k][m]
    __shared__ float Bs[16][64];   // [k][n]
    int tid = threadIdx.x;
    int tx = tid & 15, ty = tid >> 4;
    int row0 = blockIdx.x * 64;

    int arow = tid >> 2, ak = (tid & 3) << 2;   // A tile: 64 rows x 16 k
    int brow = tid >> 4, bc = (tid & 15) << 2;  // B tile: 16 k x 64 n

    float acc[4][4] = {};

    for (int k0 = 0; k0 < K; k0 += 16) {
        float4 av = make_float4(0.f, 0.f, 0.f, 0.f);
        if (row0 + arow < M)
            av = *(const float4*)&A[(size_t)(row0 + arow) * K + k0 + ak];
        As[ak + 0][arow] = av.x;
        As[ak + 1][arow] = av.y;
        As[ak + 2][arow] = av.z;
        As[ak + 3][arow] = av.w;

        float4 bv = make_float4(0.f, 0.f, 0.f, 0.f);
        if (bc < N)
            bv = *(const float4*)&B[(size_t)(k0 + brow) * N + bc];
        *(float4*)&Bs[brow][bc] = bv;

        __syncthreads();
#pragma unroll
        for (int kk = 0; kk < 16; kk++) {
            float a0 = As[kk][ty * 4 + 0];
            float a1 = As[kk][ty * 4 + 1];
            float a2 = As[kk][ty * 4 + 2];
            float a3 = As[kk][ty * 4 + 3];
            float4 b = *(float4*)&Bs[kk][tx * 4];
            acc[0][0] += a0 * b.x; acc[0][1] += a0 * b.y; acc[0][2] += a0 * b.z; acc[0][3] += a0 * b.w;
            acc[1][0] += a1 * b.x; acc[1][1] += a1 * b.y; acc[1][2] += a1 * b.z; acc[1][3] += a1 * b.w;
            acc[2][0] += a2 * b.x; acc[2][1] += a2 * b.y; acc[2][2] += a2 * b.z; acc[2][3] += a2 * b.w;
            acc[3][0] += a3 * b.x; acc[3][1] += a3 * b.y; acc[3][2] += a3 * b.z; acc[3][3] += a3 * b.w;
        }
        __syncthreads();
    }
#pragma unroll
    for (int i = 0; i < 4; i++) {
        int r = row0 + ty * 4 + i;
        if (r >= M) continue;
#pragma unroll
        for (int j = 0; j < 4; j++) {
            int c = tx * 4 + j;
            if (c < N) C[(size_t)r * N + c] = acc[i][j];
        }
    }
}

// ---------------- Layer 1 ----------------

// per node: attention logits + seed max with self-loop edge
__global__ void node_attn1(const float* __restrict__ att_src, const float* __restrict__ att_dst, int Nn) {
    int i = blockIdx.x * blockDim.x + threadIdx.x;
    if (i >= Nn) return;
    const float* h = &g_h1[i * 64];
#pragma unroll
    for (int hh = 0; hh < 8; hh++) {
        float as = 0.f, ad = 0.f;
#pragma unroll
        for (int c = 0; c < 8; c++) {
            float v = h[hh * 8 + c];
            as += v * att_src[hh * 8 + c];
            ad += v * att_dst[hh * 8 + c];
        }
        g_asrc1[i * 8 + hh] = as;
        g_adst1[i * 8 + hh] = ad;
        g_max1[i * 8 + hh] = fenc(leaky(as + ad));  // self loop seeds the max
    }
}

__global__ void edge_max1(const int* __restrict__ ei, int E) {
    int e = blockIdx.x * blockDim.x + threadIdx.x;
    if (e >= E) return;
    int s = ei[e], d = ei[E + e];
    const float* as = &g_asrc1[s * 8];
    const float* ad = &g_adst1[d * 8];
#pragma unroll
    for (int hh = 0; hh < 8; hh++) {
        float v = leaky(as[hh] + ad[hh]);
        atomicMax(&g_max1[d * 8 + hh], fenc(v));
    }
}

// decode max; initialize denom/acc with self-loop contribution
__global__ void node_self1(int Nn) {
    int t = blockIdx.x * blockDim.x + threadIdx.x;
    if (t >= Nn * 8) return;
    int i = t >> 3, hh = t & 7;
    float m = fdec(g_max1[t]);
    g_maxf1[t] = m;
    float e = leaky(g_asrc1[t] + g_adst1[t]);
    float w = __expf(e - m);
    g_denom1[t] = w;
    const float* hp = &g_h1[i * 64 + hh * 8];
    float* ap = &g_acc1[i * 64 + hh * 8];
#pragma unroll
    for (int c = 0; c < 8; c++) ap[c] = w * hp[c];
}

// one thread per (edge, head): exp weight + 8-channel atomic accumulate
__global__ void edge_acc1(const int* __restrict__ ei, int E) {
    int t = blockIdx.x * blockDim.x + threadIdx.x;
    if (t >= E * 8) return;
    int e = t >> 3, hh = t & 7;
    int s = ei[e], d = ei[E + e];
    float v = leaky(g_asrc1[s * 8 + hh] + g_adst1[d * 8 + hh]);
    float w = __expf(v - g_maxf1[d * 8 + hh]);
    atomicAdd(&g_denom1[d * 8 + hh], w);
    const float* hp = &g_h1[s * 64 + hh * 8];
    float* ap = &g_acc1[d * 64 + hh * 8];
#pragma unroll
    for (int c = 0; c < 8; c++) atomicAdd(ap + c, w * hp[c]);
}

__global__ void finalize1(const float* __restrict__ b1, int Nn) {
    int t = blockIdx.x * blockDim.x + threadIdx.x;
    if (t >= Nn * 64) return;
    int i = t >> 6, j = t & 63;
    float v = g_acc1[t] / (g_denom1[i * 8 + (j >> 3)] + 1e-16f) + b1[j];
    g_h2in[t] = v > 0.f ? v : 0.f;
}

// ---------------- Layer 2 (H=1, C=40) ----------------

__global__ void node_attn2(const float* __restrict__ att_src, const float* __restrict__ att_dst, int Nn) {
    int i = blockIdx.x * blockDim.x + threadIdx.x;
    if (i >= Nn) return;
    const float* h = &g_h2[i * 40];
    float as = 0.f, ad = 0.f;
#pragma unroll
    for (int c = 0; c < 40; c++) {
        float v = h[c];
        as += v * att_src[c];
        ad += v * att_dst[c];
    }
    g_as2[i] = as;
    g_ad2[i] = ad;
    g_max2[i] = fenc(leaky(as + ad));
}

__global__ void edge_max2(const int* __restrict__ ei, int E) {
    int e = blockIdx.x * blockDim.x + threadIdx.x;
    if (e >= E) return;
    int s = ei[e], d = ei[E + e];
    float v = leaky(g_as2[s] + g_ad2[d]);
    atomicMax(&g_max2[d], fenc(v));
}

__global__ void node_self2(int Nn) {
    int i = blockIdx.x * blockDim.x + threadIdx.x;
    if (i >= Nn) return;
    float m = fdec(g_max2[i]);
    g_maxf2[i] = m;
    float e = leaky(g_as2[i] + g_ad2[i]);
    float w = __expf(e - m);
    g_denom2[i] = w;
    const float* hp = &g_h2[i * 40];
    float* ap = &g_acc2[i * 40];
#pragma unroll
    for (int c = 0; c < 40; c++) ap[c] = w * hp[c];
}

// 10 threads per edge, each does one float4 chunk of 40 channels
__global__ void edge_acc2(const int* __restrict__ ei, int E) {
    int t = blockIdx.x * blockDim.x + threadIdx.x;
    if (t >= E * 10) return;
    int e = t / 10, sub = t - e * 10;
    int s = ei[e], d = ei[E + e];
    float v = leaky(g_as2[s] + g_ad2[d]);
    float w = __expf(v - g_maxf2[d]);
    if (sub == 0) atomicAdd(&g_denom2[d], w);
    float4 hv = *(const float4*)&g_h2[s * 40 + sub * 4];
    float* ap = &g_acc2[d * 40 + sub * 4];
    atomicAdd(ap + 0, w * hv.x);
    atomicAdd(ap + 1, w * hv.y);
    atomicAdd(ap + 2, w * hv.z);
    atomicAdd(ap + 3, w * hv.w);
}

__global__ void finalize2(const float* __restrict__ b2, float* __restrict__ out, int Nn) {
    int i = blockIdx.x * blockDim.x + threadIdx.x;
    if (i >= Nn) return;
    float den = g_denom2[i] + 1e-16f;
    float v[40];
    float mx = -1e30f;
#pragma unroll
    for (int c = 0; c < 40; c++) {
        v[c] = g_acc2[i * 40 + c] / den + b2[c];
        mx = fmaxf(mx, v[c]);
    }
    float ssum = 0.f;
#pragma unroll
    for (int c = 0; c < 40; c++) ssum += __expf(v[c] - mx);
    float lse = mx + logf(ssum);
#pragma unroll
    for (int c = 0; c < 40; c++) out[i * 40 + c] = v[c] - lse;
}

// ---------------- launch ----------------
extern "C" void kernel_launch(void* const* d_in, const int* in_sizes, int n_in,
                              void* d_out, int out_size) {
    const float* x   = (const float*)d_in[0];
    const int*   ei  = (const int*)d_in[1];   // int32 (JAX x64 disabled)
    const float* W1  = (const float*)d_in[2];
    const float* as1 = (const float*)d_in[3];
    const float* ad1 = (const float*)d_in[4];
    const float* b1  = (const float*)d_in[5];
    const float* W2  = (const float*)d_in[6];
    const float* as2 = (const float*)d_in[7];
    const float* ad2 = (const float*)d_in[8];
    const float* b2  = (const float*)d_in[9];
    float* out = (float*)d_out;

    int Nn = in_sizes[0] / 512;   // 50000
    int E  = in_sizes[1] / 2;     // 1600000

    void *ph1, *ph2in, *ph2;
    cudaGetSymbolAddress(&ph1, g_h1);
    cudaGetSymbolAddress(&ph2in, g_h2in);
    cudaGetSymbolAddress(&ph2, g_h2);

    const int T = 256;
    // layer 1
    sgemm64<<<(Nn + 63) / 64, T>>>(x, W1, (float*)ph1, Nn, 64, 512);
    node_attn1<<<(Nn + T - 1) / T, T>>>(as1, ad1, Nn);
    edge_max1<<<(E + T - 1) / T, T>>>(ei, E);
    node_self1<<<(Nn * 8 + T - 1) / T, T>>>(Nn);
    edge_acc1<<<(E * 8 + T - 1) / T, T>>>(ei, E);
    finalize1<<<(Nn * 64 + T - 1) / T, T>>>(b1, Nn);
    // layer 2
    sgemm64<<<(Nn + 63) / 64, T>>>((const float*)ph2in, W2, (float*)ph2, Nn, 40, 64);
    node_attn2<<<(Nn + T - 1) / T, T>>>(as2, ad2, Nn);
    edge_max2<<<(E + T - 1) / T, T>>>(ei, E);
    node_self2<<<(Nn + T - 1) / T, T>>>(Nn);
    edge_acc2<<<(E * 10 + T - 1) / T, T>>>(ei, E);
    finalize2<<<(Nn + T - 1) / T, T>>>(b2, out, Nn);
}

// round 2
// speedup vs baseline: 2.3825x; 2.3825x over previous
#include <cuda_runtime.h>
#include <cuda_bf16.h>

#define NMAX 50000
#define EMAX 1700000

// ---------------- scratch ----------------
__device__ float g_h1[NMAX * 64];       // x@W1
__device__ float g_asrc1[NMAX * 8];
__device__ float g_adst1[NMAX * 8];
__device__ float g_h2in[NMAX * 64];     // relu(layer1 out)
__device__ float g_h2[NMAX * 40];       // h2in@W2
__device__ float g_as2[NMAX];
__device__ float g_ad2[NMAX];
// CSR
__device__ int g_deg[NMAX];
__device__ int g_start[NMAX + 1];
__device__ int g_cursor[NMAX];
__device__ int g_csrc[EMAX];

__device__ __forceinline__ float leaky(float e) { return e >= 0.f ? e : 0.2f * e; }

// ---------------- SGEMM: C[M,N] = A[M,K] @ B[K,N], BM=64 BN=64 BK=16 ----------------
__global__ void sgemm64(const float* __restrict__ A, const float* __restrict__ B,
                        float* __restrict__ C, int M, int N, int K) {
    __shared__ float As[16][64];
    __shared__ float Bs[16][64];
    int tid = threadIdx.x;
    int tx = tid & 15, ty = tid >> 4;
    int row0 = blockIdx.x * 64;

    int arow = tid >> 2, ak = (tid & 3) << 2;
    int brow = tid >> 4, bc = (tid & 15) << 2;

    float acc[4][4] = {};

    for (int k0 = 0; k0 < K; k0 += 16) {
        float4 av = make_float4(0.f, 0.f, 0.f, 0.f);
        if (row0 + arow < M)
            av = *(const float4*)&A[(size_t)(row0 + arow) * K + k0 + ak];
        As[ak + 0][arow] = av.x;
        As[ak + 1][arow] = av.y;
        As[ak + 2][arow] = av.z;
        As[ak + 3][arow] = av.w;

        float4 bv = make_float4(0.f, 0.f, 0.f, 0.f);
        if (bc < N)
            bv = *(const float4*)&B[(size_t)(k0 + brow) * N + bc];
        *(float4*)&Bs[brow][bc] = bv;

        __syncthreads();
#pragma unroll
        for (int kk = 0; kk < 16; kk++) {
            float a0 = As[kk][ty * 4 + 0];
            float a1 = As[kk][ty * 4 + 1];
            float a2 = As[kk][ty * 4 + 2];
            float a3 = As[kk][ty * 4 + 3];
            float4 b = *(float4*)&Bs[kk][tx * 4];
            acc[0][0] += a0 * b.x; acc[0][1] += a0 * b.y; acc[0][2] += a0 * b.z; acc[0][3] += a0 * b.w;
            acc[1][0] += a1 * b.x; acc[1][1] += a1 * b.y; acc[1][2] += a1 * b.z; acc[1][3] += a1 * b.w;
            acc[2][0] += a2 * b.x; acc[2][1] += a2 * b.y; acc[2][2] += a2 * b.z; acc[2][3] += a2 * b.w;
            acc[3][0] += a3 * b.x; acc[3][1] += a3 * b.y; acc[3][2] += a3 * b.z; acc[3][3] += a3 * b.w;
        }
        __syncthreads();
    }
#pragma unroll
    for (int i = 0; i < 4; i++) {
        int r = row0 + ty * 4 + i;
        if (r >= M) continue;
#pragma unroll
        for (int j = 0; j < 4; j++) {
            int c = tx * 4 + j;
            if (c < N) C[(size_t)r * N + c] = acc[i][j];
        }
    }
}

// ---------------- CSR build ----------------
__global__ void zero_deg(int Nn) {
    int i = blockIdx.x * blockDim.x + threadIdx.x;
    if (i < Nn) g_deg[i] = 0;
}

__global__ void hist_dst(const int* __restrict__ ei, int E) {
    int e = blockIdx.x * blockDim.x + threadIdx.x;
    if (e < E) atomicAdd(&g_deg[ei[E + e]], 1);
}

// single-block exclusive scan (warp-shuffle based), writes g_start & g_cursor
__global__ void scan_deg(int Nn) {
    __shared__ int warpsum[32];
    __shared__ int carry_s;
    int lane = threadIdx.x & 31, wid = threadIdx.x >> 5;
    if (threadIdx.x == 0) carry_s = 0;
    __syncthreads();
    for (int base = 0; base < Nn; base += 1024) {
        int i = base + threadIdx.x;
        int v = (i < Nn) ? g_deg[i] : 0;
        int sc = v;
#pragma unroll
        for (int o = 1; o < 32; o <<= 1) {
            int t = __shfl_up_sync(~0u, sc, o);
            if (lane >= o) sc += t;
        }
        if (lane == 31) warpsum[wid] = sc;
        __syncthreads();
        if (wid == 0) {
            int ws = warpsum[lane];
#pragma unroll
            for (int o = 1; o < 32; o <<= 1) {
                int t = __shfl_up_sync(~0u, ws, o);
                if (lane >= o) ws += t;
            }
            warpsum[lane] = ws;
        }
        __syncthreads();
        int prefix = carry_s + (wid > 0 ? warpsum[wid - 1] : 0) + sc - v;
        if (i < Nn) { g_start[i] = prefix; g_cursor[i] = prefix; }
        __syncthreads();
        if (threadIdx.x == 0) carry_s += warpsum[31];
        __syncthreads();
    }
    if (threadIdx.x == 0) g_start[Nn] = carry_s;
}

__global__ void scatter_csr(const int* __restrict__ ei, int E) {
    int e = blockIdx.x * blockDim.x + threadIdx.x;
    if (e >= E) return;
    int d = ei[E + e];
    int pos = atomicAdd(&g_cursor[d], 1);
    g_csrc[pos] = ei[e];
}

// ---------------- attention logits ----------------
__global__ void node_attn1(const float* __restrict__ att_src, const float* __restrict__ att_dst, int Nn) {
    int i = blockIdx.x * blockDim.x + threadIdx.x;
    if (i >= Nn) return;
    const float* h = &g_h1[i * 64];
#pragma unroll
    for (int hh = 0; hh < 8; hh++) {
        float as = 0.f, ad = 0.f;
#pragma unroll
        for (int c = 0; c < 8; c++) {
            float v = h[hh * 8 + c];
            as += v * att_src[hh * 8 + c];
            ad += v * att_dst[hh * 8 + c];
        }
        g_asrc1[i * 8 + hh] = as;
        g_adst1[i * 8 + hh] = ad;
    }
}

__global__ void node_attn2(const float* __restrict__ att_src, const float* __restrict__ att_dst, int Nn) {
    int i = blockIdx.x * blockDim.x + threadIdx.x;
    if (i >= Nn) return;
    const float* h = &g_h2[i * 40];
    float as = 0.f, ad = 0.f;
#pragma unroll
    for (int c = 0; c < 40; c++) {
        float v = h[c];
        as += v * att_src[c];
        ad += v * att_dst[c];
    }
    g_as2[i] = as;
    g_ad2[i] = ad;
}

// ---------------- Layer 1 fused aggregation + softmax + bias + relu ----------------
// one block (64 threads) per dst node; channel = tid, head = tid>>3
__global__ void agg1(const float* __restrict__ b1) {
    int i = blockIdx.x;
    int tid = threadIdx.x;
    int h = tid >> 3;
    __shared__ int s_src[8];
    __shared__ float s_w[64];     // [edge][head]
    __shared__ float s_adst[8];
    if (tid < 8) s_adst[tid] = g_adst1[i * 8 + tid];
    __syncthreads();

    // self loop
    float w = __expf(leaky(g_asrc1[i * 8 + h] + s_adst[h]));
    float denom = w;
    float acc = w * g_h1[i * 64 + tid];

    int st = g_start[i], en = g_start[i + 1];
    for (int e0 = st; e0 < en; e0 += 8) {
        if (tid < 8) {
            int idx = e0 + tid;
            s_src[tid] = (idx < en) ? g_csrc[idx] : 0;
        }
        __syncthreads();
        {
            int ee = tid >> 3, hh = tid & 7;
            int s = s_src[ee];
            s_w[tid] = (e0 + ee < en) ? __expf(leaky(g_asrc1[s * 8 + hh] + s_adst[hh])) : 0.f;
        }
        __syncthreads();
#pragma unroll
        for (int j = 0; j < 8; j++) {
            int s2 = s_src[j];
            float wj = s_w[j * 8 + h];
            acc += wj * g_h1[s2 * 64 + tid];
            denom += wj;
        }
        __syncthreads();
    }
    float v = acc / (denom + 1e-16f) + b1[tid];
    g_h2in[i * 64 + tid] = v > 0.f ? v : 0.f;
}

// ---------------- Layer 2 fused aggregation + softmax + bias + log_softmax ----------------
// one block (64 threads) per dst node; threads 0..39 own channels
__global__ void agg2(const float* __restrict__ b2, float* __restrict__ out) {
    int i = blockIdx.x;
    int tid = threadIdx.x;
    __shared__ int s_src[16];
    __shared__ float s_w[16];
    __shared__ float s_v[40];

    float ad = g_ad2[i];
    float wself = __expf(leaky(g_as2[i] + ad));
    float denom = wself;
    float acc = (tid < 40) ? wself * g_h2[i * 40 + tid] : 0.f;

    int st = g_start[i], en = g_start[i + 1];
    for (int e0 = st; e0 < en; e0 += 16) {
        if (tid < 16) {
            int idx = e0 + tid;
            int s = (idx < en) ? g_csrc[idx] : 0;
            s_src[tid] = s;
            s_w[tid] = (idx < en) ? __expf(leaky(g_as2[s] + ad)) : 0.f;
        }
        __syncthreads();
        if (tid < 40) {
#pragma unroll
            for (int j = 0; j < 16; j++) {
                float wj = s_w[j];
                acc += wj * g_h2[s_src[j] * 40 + tid];
                denom += wj;
            }
        }
        __syncthreads();
    }

    if (tid < 40) s_v[tid] = acc / (denom + 1e-16f) + b2[tid];
    __syncthreads();
    if (tid < 40) {
        float v = s_v[tid];
        float mx = -1e30f;
#pragma unroll
        for (int c = 0; c < 40; c++) mx = fmaxf(mx, s_v[c]);
        float ssum = 0.f;
#pragma unroll
        for (int c = 0; c < 40; c++) ssum += __expf(s_v[c] - mx);
        out[i * 40 + tid] = v - (mx + logf(ssum));
    }
}

// ---------------- launch ----------------
extern "C" void kernel_launch(void* const* d_in, const int* in_sizes, int n_in,
                              void* d_out, int out_size) {
    const float* x   = (const float*)d_in[0];
    const int*   ei  = (const int*)d_in[1];
    const float* W1  = (const float*)d_in[2];
    const float* as1 = (const float*)d_in[3];
    const float* ad1 = (const float*)d_in[4];
    const float* b1  = (const float*)d_in[5];
    const float* W2  = (const float*)d_in[6];
    const float* as2 = (const float*)d_in[7];
    const float* ad2 = (const float*)d_in[8];
    const float* b2  = (const float*)d_in[9];
    float* out = (float*)d_out;

    int Nn = in_sizes[0] / 512;   // 50000
    int E  = in_sizes[1] / 2;     // 1600000

    void *ph1, *ph2in, *ph2;
    cudaGetSymbolAddress(&ph1, g_h1);
    cudaGetSymbolAddress(&ph2in, g_h2in);
    cudaGetSymbolAddress(&ph2, g_h2);

    const int T = 256;
    // CSR build (shared by both layers)
    zero_deg<<<(Nn + T - 1) / T, T>>>(Nn);
    hist_dst<<<(E + T - 1) / T, T>>>(ei, E);
    scan_deg<<<1, 1024>>>(Nn);
    scatter_csr<<<(E + T - 1) / T, T>>>(ei, E);

    // layer 1
    sgemm64<<<(Nn + 63) / 64, T>>>(x, W1, (float*)ph1, Nn, 64, 512);
    node_attn1<<<(Nn + T - 1) / T, T>>>(as1, ad1, Nn);
    agg1<<<Nn, 64>>>(b1);

    // layer 2
    sgemm64<<<(Nn + 63) / 64, T>>>((const float*)ph2in, W2, (float*)ph2, Nn, 40, 64);
    node_attn2<<<(Nn + T - 1) / T, T>>>(as2, ad2, Nn);
    agg2<<<Nn, 64>>>(b2, out);
}

// round 4
// speedup vs baseline: 2.7922x; 1.1719x over previous
#include <cuda_runtime.h>
#include <cuda_bf16.h>

#define NMAX 50000
#define EMAX 1700000

// ---------------- scratch ----------------
__device__ float g_h1[NMAX * 64];       // x@W1
__device__ float g_asrc1[NMAX * 8];
__device__ float g_adst1[NMAX * 8];
__device__ float g_h2in[NMAX * 64];     // relu(layer1 out)
__device__ float g_h2[NMAX * 40];       // h2in@W2
__device__ float g_as2[NMAX];
__device__ float g_ad2[NMAX];
// CSR
__device__ int g_deg[NMAX];
__device__ int g_start[NMAX + 1];
__device__ int g_cursor[NMAX];
__device__ int g_csrc[EMAX];
__device__ int g_bsum[64];

__device__ __forceinline__ float leaky(float e) { return e >= 0.f ? e : 0.2f * e; }

// ---------------- SGEMM1: C[M,64] = A[M,512] @ B[512,64], BM=128 BN=64 BK=16 ----------------
// 256 threads, 8x4 microtile, double-buffered smem.
__global__ void __launch_bounds__(256) sgemm1k(const float* __restrict__ A,
                                               const float* __restrict__ B,
                                               float* __restrict__ C, int M) {
    const int K = 512, N = 64;
    __shared__ float As[2][16][128];
    __shared__ float Bs[2][16][64];
    int tid = threadIdx.x;
    int tx = tid & 15, ty = tid >> 4;
    int row0 = blockIdx.x * 128;

    int arow = tid >> 1, ak = (tid & 1) * 8;   // A: 128 rows x 16 k, 2 float4/thread
    int brow = tid >> 4, bc = (tid & 15) * 4;  // B: 16 k x 64 n, 1 float4/thread

    int aRowG = row0 + arow;
    if (aRowG >= M) aRowG = M - 1;  // clamp (extra rows computed, never stored)
    const float* Arow = A + (size_t)aRowG * K;

    float acc[8][4] = {};

    // preload tile 0
    {
        float4 v0 = *(const float4*)&Arow[ak];
        float4 v1 = *(const float4*)&Arow[ak + 4];
        As[0][ak + 0][arow] = v0.x; As[0][ak + 1][arow] = v0.y;
        As[0][ak + 2][arow] = v0.z; As[0][ak + 3][arow] = v0.w;
        As[0][ak + 4][arow] = v1.x; As[0][ak + 5][arow] = v1.y;
        As[0][ak + 6][arow] = v1.z; As[0][ak + 7][arow] = v1.w;
        *(float4*)&Bs[0][brow][bc] = *(const float4*)&B[(size_t)brow * N + bc];
    }
    __syncthreads();

    int buf = 0;
    for (int k0 = 0; k0 < K; k0 += 16, buf ^= 1) {
        if (k0 + 16 < K) {
            float4 v0 = *(const float4*)&Arow[k0 + 16 + ak];
            float4 v1 = *(const float4*)&Arow[k0 + 16 + ak + 4];
            int nb = buf ^ 1;
            As[nb][ak + 0][arow] = v0.x; As[nb][ak + 1][arow] = v0.y;
            As[nb][ak + 2][arow] = v0.z; As[nb][ak + 3][arow] = v0.w;
            As[nb][ak + 4][arow] = v1.x; As[nb][ak + 5][arow] = v1.y;
            As[nb][ak + 6][arow] = v1.z; As[nb][ak + 7][arow] = v1.w;
            *(float4*)&Bs[nb][brow][bc] = *(const float4*)&B[(size_t)(k0 + 16 + brow) * N + bc];
        }
#pragma unroll
        for (int kk = 0; kk < 16; kk++) {
            float a[8];
#pragma unroll
            for (int i = 0; i < 8; i++) a[i] = As[buf][kk][ty * 8 + i];
            float4 b = *(float4*)&Bs[buf][kk][tx * 4];
#pragma unroll
            for (int i = 0; i < 8; i++) {
                acc[i][0] += a[i] * b.x;
                acc[i][1] += a[i] * b.y;
                acc[i][2] += a[i] * b.z;
                acc[i][3] += a[i] * b.w;
            }
        }
        __syncthreads();
    }

#pragma unroll
    for (int i = 0; i < 8; i++) {
        int r = row0 + ty * 8 + i;
        if (r < M) *(float4*)&C[(size_t)r * N + tx * 4] = *(float4*)acc[i];
    }
}

// ---------------- SGEMM: C[M,N] = A[M,K] @ B[K,N], BM=64 BN=64 BK=16 (layer 2) ----------------
__global__ void sgemm64(const float* __restrict__ A, const float* __restrict__ B,
                        float* __restrict__ C, int M, int N, int K) {
    __shared__ float As[16][64];
    __shared__ float Bs[16][64];
    int tid = threadIdx.x;
    int tx = tid & 15, ty = tid >> 4;
    int row0 = blockIdx.x * 64;

    int arow = tid >> 2, ak = (tid & 3) << 2;
    int brow = tid >> 4, bc = (tid & 15) << 2;

    float acc[4][4] = {};

    for (int k0 = 0; k0 < K; k0 += 16) {
        float4 av = make_float4(0.f, 0.f, 0.f, 0.f);
        if (row0 + arow < M)
            av = *(const float4*)&A[(size_t)(row0 + arow) * K + k0 + ak];
        As[ak + 0][arow] = av.x;
        As[ak + 1][arow] = av.y;
        As[ak + 2][arow] = av.z;
        As[ak + 3][arow] = av.w;

        float4 bv = make_float4(0.f, 0.f, 0.f, 0.f);
        if (bc < N)
            bv = *(const float4*)&B[(size_t)(k0 + brow) * N + bc];
        *(float4*)&Bs[brow][bc] = bv;

        __syncthreads();
#pragma unroll
        for (int kk = 0; kk < 16; kk++) {
            float a0 = As[kk][ty * 4 + 0];
            float a1 = As[kk][ty * 4 + 1];
            float a2 = As[kk][ty * 4 + 2];
            float a3 = As[kk][ty * 4 + 3];
            float4 b = *(float4*)&Bs[kk][tx * 4];
            acc[0][0] += a0 * b.x; acc[0][1] += a0 * b.y; acc[0][2] += a0 * b.z; acc[0][3] += a0 * b.w;
            acc[1][0] += a1 * b.x; acc[1][1] += a1 * b.y; acc[1][2] += a1 * b.z; acc[1][3] += a1 * b.w;
            acc[2][0] += a2 * b.x; acc[2][1] += a2 * b.y; acc[2][2] += a2 * b.z; acc[2][3] += a2 * b.w;
            acc[3][0] += a3 * b.x; acc[3][1] += a3 * b.y; acc[3][2] += a3 * b.z; acc[3][3] += a3 * b.w;
        }
        __syncthreads();
    }
#pragma unroll
    for (int i = 0; i < 4; i++) {
        int r = row0 + ty * 4 + i;
        if (r >= M) continue;
#pragma unroll
        for (int j = 0; j < 4; j++) {
            int c = tx * 4 + j;
            if (c < N) C[(size_t)r * N + c] = acc[i][j];
        }
    }
}

// ---------------- CSR build ----------------
__global__ void hist_dst(const int* __restrict__ ei, int E) {
    int e = blockIdx.x * blockDim.x + threadIdx.x;
    if (e < E) atomicAdd(&g_deg[ei[E + e]], 1);
}

// phase 1: per-1024-chunk local exclusive scan + chunk totals
__global__ void scan_local(int Nn) {
    __shared__ int wsum[32];
    int i = blockIdx.x * 1024 + threadIdx.x;
    int lane = threadIdx.x & 31, wid = threadIdx.x >> 5;
    int v = (i < Nn) ? g_deg[i] : 0;
    int sc = v;
#pragma unroll
    for (int o = 1; o < 32; o <<= 1) {
        int t = __shfl_up_sync(~0u, sc, o);
        if (lane >= o) sc += t;
    }
    if (lane == 31) wsum[wid] = sc;
    __syncthreads();
    if (wid == 0) {
        int ws = wsum[lane];
#pragma unroll
        for (int o = 1; o < 32; o <<= 1) {
            int t = __shfl_up_sync(~0u, ws, o);
            if (lane >= o) ws += t;
        }
        wsum[lane] = ws;
    }
    __syncthreads();
    int excl = sc - v + (wid > 0 ? wsum[wid - 1] : 0);
    if (i < Nn) g_start[i] = excl;
    if (threadIdx.x == 1023) g_bsum[blockIdx.x] = excl + v;
}

// phase 2: single warp scans chunk totals (<=64 chunks)
__global__ void scan_spine(int nb, int Nn) {
    int lane = threadIdx.x;
    int v0 = (lane * 2 < nb) ? g_bsum[lane * 2] : 0;
    int v1 = (lane * 2 + 1 < nb) ? g_bsum[lane * 2 + 1] : 0;
    int s = v0 + v1;
    int sc = s;
#pragma unroll
    for (int o = 1; o < 32; o <<= 1) {
        int t = __shfl_up_sync(~0u, sc, o);
        if (lane >= o) sc += t;
    }
    int excl = sc - s;
    if (lane * 2 < nb) g_bsum[lane * 2] = excl;
    if (lane * 2 + 1 < nb) g_bsum[lane * 2 + 1] = excl + v0;
    if (lane == 31) g_start[Nn] = sc;
}

// phase 3: add chunk offset, materialize cursor
__global__ void scan_add(int Nn) {
    int i = blockIdx.x * blockDim.x + threadIdx.x;
    if (i >= Nn) return;
    int s = g_start[i] + g_bsum[i >> 10];
    g_start[i] = s;
    g_cursor[i] = s;
}

__global__ void scatter_csr(const int* __restrict__ ei, int E) {
    int e = blockIdx.x * blockDim.x + threadIdx.x;
    if (e >= E) return;
    int d = ei[E + e];
    int pos = atomicAdd(&g_cursor[d], 1);
    g_csrc[pos] = ei[e];
}

// ---------------- attention logits ----------------
__global__ void node_attn1(const float* __restrict__ att_src, const float* __restrict__ att_dst, int Nn) {
    int i = blockIdx.x * blockDim.x + threadIdx.x;
    if (i >= Nn) return;
    const float* h = &g_h1[i * 64];
#pragma unroll
    for (int hh = 0; hh < 8; hh++) {
        float as = 0.f, ad = 0.f;
#pragma unroll
        for (int c = 0; c < 8; c++) {
            float v = h[hh * 8 + c];
            as += v * att_src[hh * 8 + c];
            ad += v * att_dst[hh * 8 + c];
        }
        g_asrc1[i * 8 + hh] = as;
        g_adst1[i * 8 + hh] = ad;
    }
}

__global__ void node_attn2(const float* __restrict__ att_src, const float* __restrict__ att_dst, int Nn) {
    int i = blockIdx.x * blockDim.x + threadIdx.x;
    if (i >= Nn) return;
    const float* h = &g_h2[i * 40];
    float as = 0.f, ad = 0.f;
#pragma unroll
    for (int c = 0; c < 40; c++) {
        float v = h[c];
        as += v * att_src[c];
        ad += v * att_dst[c];
    }
    g_as2[i] = as;
    g_ad2[i] = ad;
}

// ---------------- Layer 1 fused aggregation + softmax + bias + relu ----------------
__global__ void agg1(const float* __restrict__ b1) {
    int i = blockIdx.x;
    int tid = threadIdx.x;
    int h = tid >> 3;
    __shared__ int s_src[8];
    __shared__ float s_w[64];
    __shared__ float s_adst[8];
    if (tid < 8) s_adst[tid] = g_adst1[i * 8 + tid];
    __syncthreads();

    float w = __expf(leaky(g_asrc1[i * 8 + h] + s_adst[h]));
    float denom = w;
    float acc = w * g_h1[i * 64 + tid];

    int st = g_start[i], en = g_start[i + 1];
    for (int e0 = st; e0 < en; e0 += 8) {
        if (tid < 8) {
            int idx = e0 + tid;
            s_src[tid] = (idx < en) ? g_csrc[idx] : 0;
        }
        __syncthreads();
        {
            int ee = tid >> 3, hh = tid & 7;
            int s = s_src[ee];
            s_w[tid] = (e0 + ee < en) ? __expf(leaky(g_asrc1[s * 8 + hh] + s_adst[hh])) : 0.f;
        }
        __syncthreads();
#pragma unroll
        for (int j = 0; j < 8; j++) {
            int s2 = s_src[j];
            float wj = s_w[j * 8 + h];
            acc += wj * g_h1[s2 * 64 + tid];
            denom += wj;
        }
        __syncthreads();
    }
    float v = acc / (denom + 1e-16f) + b1[tid];
    g_h2in[i * 64 + tid] = v > 0.f ? v : 0.f;
}

// ---------------- Layer 2 fused aggregation + softmax + bias + log_softmax ----------------
__global__ void agg2(const float* __restrict__ b2, float* __restrict__ out) {
    int i = blockIdx.x;
    int tid = threadIdx.x;
    __shared__ int s_src[16];
    __shared__ float s_w[16];
    __shared__ float s_v[40];

    float ad = g_ad2[i];
    float wself = __expf(leaky(g_as2[i] + ad));
    float denom = wself;
    float acc = (tid < 40) ? wself * g_h2[i * 40 + tid] : 0.f;

    int st = g_start[i], en = g_start[i + 1];
    for (int e0 = st; e0 < en; e0 += 16) {
        if (tid < 16) {
            int idx = e0 + tid;
            int s = (idx < en) ? g_csrc[idx] : 0;
            s_src[tid] = s;
            s_w[tid] = (idx < en) ? __expf(leaky(g_as2[s] + ad)) : 0.f;
        }
        __syncthreads();
        if (tid < 40) {
#pragma unroll
            for (int j = 0; j < 16; j++) {
                float wj = s_w[j];
                acc += wj * g_h2[s_src[j] * 40 + tid];
                denom += wj;
            }
        }
        __syncthreads();
    }

    if (tid < 40) s_v[tid] = acc / (denom + 1e-16f) + b2[tid];
    __syncthreads();
    if (tid < 40) {
        float v = s_v[tid];
        float mx = -1e30f;
#pragma unroll
        for (int c = 0; c < 40; c++) mx = fmaxf(mx, s_v[c]);
        float ssum = 0.f;
#pragma unroll
        for (int c = 0; c < 40; c++) ssum += __expf(s_v[c] - mx);
        out[i * 40 + tid] = v - (mx + logf(ssum));
    }
}

// ---------------- launch ----------------
extern "C" void kernel_launch(void* const* d_in, const int* in_sizes, int n_in,
                              void* d_out, int out_size) {
    const float* x   = (const float*)d_in[0];
    const int*   ei  = (const int*)d_in[1];
    const float* W1  = (const float*)d_in[2];
    const float* as1 = (const float*)d_in[3];
    const float* ad1 = (const float*)d_in[4];
    const float* b1  = (const float*)d_in[5];
    const float* W2  = (const float*)d_in[6];
    const float* as2 = (const float*)d_in[7];
    const float* ad2 = (const float*)d_in[8];
    const float* b2  = (const float*)d_in[9];
    float* out = (float*)d_out;

    int Nn = in_sizes[0] / 512;   // 50000
    int E  = in_sizes[1] / 2;     // 1600000

    void *ph1, *ph2in, *ph2, *pdeg;
    cudaGetSymbolAddress(&ph1, g_h1);
    cudaGetSymbolAddress(&ph2in, g_h2in);
    cudaGetSymbolAddress(&ph2, g_h2);
    cudaGetSymbolAddress(&pdeg, g_deg);

    const int T = 256;
    int nChunks = (Nn + 1023) / 1024;

    // CSR build (shared by both layers)
    cudaMemsetAsync(pdeg, 0, (size_t)Nn * sizeof(int));
    hist_dst<<<(E + T - 1) / T, T>>>(ei, E);
    scan_local<<<nChunks, 1024>>>(Nn);
    scan_spine<<<1, 32>>>(nChunks, Nn);
    scan_add<<<(Nn + T - 1) / T, T>>>(Nn);
    scatter_csr<<<(E + T - 1) / T, T>>>(ei, E);

    // layer 1
    sgemm1k<<<(Nn + 127) / 128, T>>>(x, W1, (float*)ph1, Nn);
    node_attn1<<<(Nn + T - 1) / T, T>>>(as1, ad1, Nn);
    agg1<<<Nn, 64>>>(b1);

    // layer 2
    sgemm64<<<(Nn + 63) / 64, T>>>((const float*)ph2in, W2, (float*)ph2, Nn, 40, 64);
    node_attn2<<<(Nn + T - 1) / T, T>>>(as2, ad2, Nn);
    agg2<<<Nn, 64>>>(b2, out);
}

// round 5
// speedup vs baseline: 3.5229x; 1.2617x over previous
#include <cuda_runtime.h>
#include <cuda_bf16.h>

#define NMAX 50000
#define EMAX 1700000

// ---------------- scratch ----------------
__device__ float g_h1[NMAX * 64];       // x@W1
__device__ float g_asrc1[NMAX * 8];
__device__ float g_adst1[NMAX * 8];
__device__ float g_h2in[NMAX * 64];     // relu(layer1 out)
__device__ float g_h2[NMAX * 40];       // h2in@W2
__device__ float g_as2[NMAX];
__device__ float g_ad2[NMAX];
// CSR
__device__ int g_deg[NMAX];
__device__ int g_start[NMAX + 1];
__device__ int g_cursor[NMAX];
__device__ int g_csrc[EMAX];
__device__ int g_bsum[64];

__device__ __forceinline__ float leaky(float e) { return e >= 0.f ? e : 0.2f * e; }

// ---------------- SGEMM1: C[M,64] = A[M,512] @ B[512,64] + fused attn logits ----------------
// BM=128 BN=64 BK=16, 128 threads, 8x8 microtile, double-buffered.
__global__ void __launch_bounds__(128) sgemm1k(const float* __restrict__ A,
                                               const float* __restrict__ B,
                                               float* __restrict__ C,
                                               const float* __restrict__ att_src,
                                               const float* __restrict__ att_dst,
                                               int M) {
    const int K = 512, N = 64;
    __shared__ float As[2][16][128];
    __shared__ float Bs[2][16][64];
    int tid = threadIdx.x;
    int tx = tid & 7, ty = tid >> 3;          // 16 x 8 thread grid
    int row0 = blockIdx.x * 128;

    int aRowG = row0 + tid;
    if (aRowG >= M) aRowG = M - 1;            // clamp; extra rows never stored
    const float* Arow = A + (size_t)aRowG * K;

    int brow = tid >> 3, bc = (tid & 7) * 8;  // B: 16k x 64n, 2 float4/thread

    float acc[8][8] = {};
    float4 rA[4], rB0, rB1;

    // preload tile 0
    {
        rA[0] = *(const float4*)&Arow[0];
        rA[1] = *(const float4*)&Arow[4];
        rA[2] = *(const float4*)&Arow[8];
        rA[3] = *(const float4*)&Arow[12];
        rB0 = *(const float4*)&B[(size_t)brow * N + bc];
        rB1 = *(const float4*)&B[(size_t)brow * N + bc + 4];
#pragma unroll
        for (int q = 0; q < 4; q++) {
            As[0][q * 4 + 0][tid] = ((float*)&rA[q])[0];
            As[0][q * 4 + 1][tid] = ((float*)&rA[q])[1];
            As[0][q * 4 + 2][tid] = ((float*)&rA[q])[2];
            As[0][q * 4 + 3][tid] = ((float*)&rA[q])[3];
        }
        *(float4*)&Bs[0][brow][bc] = rB0;
        *(float4*)&Bs[0][brow][bc + 4] = rB1;
    }
    __syncthreads();

    int buf = 0;
    for (int k0 = 0; k0 < K; k0 += 16, buf ^= 1) {
        bool more = (k0 + 16 < K);
        if (more) {
            rA[0] = *(const float4*)&Arow[k0 + 16];
            rA[1] = *(const float4*)&Arow[k0 + 20];
            rA[2] = *(const float4*)&Arow[k0 + 24];
            rA[3] = *(const float4*)&Arow[k0 + 28];
            rB0 = *(const float4*)&B[(size_t)(k0 + 16 + brow) * N + bc];
            rB1 = *(const float4*)&B[(size_t)(k0 + 16 + brow) * N + bc + 4];
        }
#pragma unroll
        for (int kk = 0; kk < 16; kk++) {
            float a[8], b[8];
            *(float4*)&a[0] = *(float4*)&As[buf][kk][ty * 8];
            *(float4*)&a[4] = *(float4*)&As[buf][kk][ty * 8 + 4];
            *(float4*)&b[0] = *(float4*)&Bs[buf][kk][tx * 8];
            *(float4*)&b[4] = *(float4*)&Bs[buf][kk][tx * 8 + 4];
#pragma unroll
            for (int i = 0; i < 8; i++)
#pragma unroll
                for (int j = 0; j < 8; j++)
                    acc[i][j] += a[i] * b[j];
        }
        if (more) {
            int nb = buf ^ 1;
#pragma unroll
            for (int q = 0; q < 4; q++) {
                As[nb][q * 4 + 0][tid] = ((float*)&rA[q])[0];
                As[nb][q * 4 + 1][tid] = ((float*)&rA[q])[1];
                As[nb][q * 4 + 2][tid] = ((float*)&rA[q])[2];
                As[nb][q * 4 + 3][tid] = ((float*)&rA[q])[3];
            }
            *(float4*)&Bs[nb][brow][bc] = rB0;
            *(float4*)&Bs[nb][brow][bc + 4] = rB1;
        }
        __syncthreads();
    }

    // epilogue: store C + fused per-head attn logits (head == tx)
    float asv[8], adv[8];
#pragma unroll
    for (int j = 0; j < 8; j++) {
        asv[j] = att_src[tx * 8 + j];
        adv[j] = att_dst[tx * 8 + j];
    }
#pragma unroll
    for (int i = 0; i < 8; i++) {
        int r = row0 + ty * 8 + i;
        if (r < M) {
            *(float4*)&C[(size_t)r * N + tx * 8] = *(float4*)&acc[i][0];
            *(float4*)&C[(size_t)r * N + tx * 8 + 4] = *(float4*)&acc[i][4];
            float as = 0.f, ad = 0.f;
#pragma unroll
            for (int j = 0; j < 8; j++) {
                as += acc[i][j] * asv[j];
                ad += acc[i][j] * adv[j];
            }
            g_asrc1[r * 8 + tx] = as;
            g_adst1[r * 8 + tx] = ad;
        }
    }
}

// ---------------- SGEMM: C[M,N] = A[M,K] @ B[K,N], BM=64 BN=64 BK=16 (layer 2) ----------------
__global__ void sgemm64(const float* __restrict__ A, const float* __restrict__ B,
                        float* __restrict__ C, int M, int N, int K) {
    __shared__ float As[16][64];
    __shared__ float Bs[16][64];
    int tid = threadIdx.x;
    int tx = tid & 15, ty = tid >> 4;
    int row0 = blockIdx.x * 64;

    int arow = tid >> 2, ak = (tid & 3) << 2;
    int brow = tid >> 4, bc = (tid & 15) << 2;

    float acc[4][4] = {};

    for (int k0 = 0; k0 < K; k0 += 16) {
        float4 av = make_float4(0.f, 0.f, 0.f, 0.f);
        if (row0 + arow < M)
            av = *(const float4*)&A[(size_t)(row0 + arow) * K + k0 + ak];
        As[ak + 0][arow] = av.x;
        As[ak + 1][arow] = av.y;
        As[ak + 2][arow] = av.z;
        As[ak + 3][arow] = av.w;

        float4 bv = make_float4(0.f, 0.f, 0.f, 0.f);
        if (bc < N)
            bv = *(const float4*)&B[(size_t)(k0 + brow) * N + bc];
        *(float4*)&Bs[brow][bc] = bv;

        __syncthreads();
#pragma unroll
        for (int kk = 0; kk < 16; kk++) {
            float a0 = As[kk][ty * 4 + 0];
            float a1 = As[kk][ty * 4 + 1];
            float a2 = As[kk][ty * 4 + 2];
            float a3 = As[kk][ty * 4 + 3];
            float4 b = *(float4*)&Bs[kk][tx * 4];
            acc[0][0] += a0 * b.x; acc[0][1] += a0 * b.y; acc[0][2] += a0 * b.z; acc[0][3] += a0 * b.w;
            acc[1][0] += a1 * b.x; acc[1][1] += a1 * b.y; acc[1][2] += a1 * b.z; acc[1][3] += a1 * b.w;
            acc[2][0] += a2 * b.x; acc[2][1] += a2 * b.y; acc[2][2] += a2 * b.z; acc[2][3] += a2 * b.w;
            acc[3][0] += a3 * b.x; acc[3][1] += a3 * b.y; acc[3][2] += a3 * b.z; acc[3][3] += a3 * b.w;
        }
        __syncthreads();
    }
#pragma unroll
    for (int i = 0; i < 4; i++) {
        int r = row0 + ty * 4 + i;
        if (r >= M) continue;
#pragma unroll
        for (int j = 0; j < 4; j++) {
            int c = tx * 4 + j;
            if (c < N) C[(size_t)r * N + c] = acc[i][j];
        }
    }
}

// ---------------- CSR build ----------------
__global__ void hist_dst(const int* __restrict__ ei, int E) {
    int e = blockIdx.x * blockDim.x + threadIdx.x;
    if (e < E) atomicAdd(&g_deg[ei[E + e]], 1);
}

__global__ void scan_local(int Nn) {
    __shared__ int wsum[32];
    int i = blockIdx.x * 1024 + threadIdx.x;
    int lane = threadIdx.x & 31, wid = threadIdx.x >> 5;
    int v = (i < Nn) ? g_deg[i] : 0;
    int sc = v;
#pragma unroll
    for (int o = 1; o < 32; o <<= 1) {
        int t = __shfl_up_sync(~0u, sc, o);
        if (lane >= o) sc += t;
    }
    if (lane == 31) wsum[wid] = sc;
    __syncthreads();
    if (wid == 0) {
        int ws = wsum[lane];
#pragma unroll
        for (int o = 1; o < 32; o <<= 1) {
            int t = __shfl_up_sync(~0u, ws, o);
            if (lane >= o) ws += t;
        }
        wsum[lane] = ws;
    }
    __syncthreads();
    int excl = sc - v + (wid > 0 ? wsum[wid - 1] : 0);
    if (i < Nn) g_start[i] = excl;
    if (threadIdx.x == 1023) g_bsum[blockIdx.x] = excl + v;
}

__global__ void scan_spine(int nb, int Nn) {
    int lane = threadIdx.x;
    int v0 = (lane * 2 < nb) ? g_bsum[lane * 2] : 0;
    int v1 = (lane * 2 + 1 < nb) ? g_bsum[lane * 2 + 1] : 0;
    int s = v0 + v1;
    int sc = s;
#pragma unroll
    for (int o = 1; o < 32; o <<= 1) {
        int t = __shfl_up_sync(~0u, sc, o);
        if (lane >= o) sc += t;
    }
    int excl = sc - s;
    if (lane * 2 < nb) g_bsum[lane * 2] = excl;
    if (lane * 2 + 1 < nb) g_bsum[lane * 2 + 1] = excl + v0;
    if (lane == 31) g_start[Nn] = sc;
}

__global__ void scan_add(int Nn) {
    int i = blockIdx.x * blockDim.x + threadIdx.x;
    if (i >= Nn) return;
    int s = g_start[i] + g_bsum[i >> 10];
    g_start[i] = s;
    g_cursor[i] = s;
}

__global__ void scatter_csr(const int* __restrict__ ei, int E) {
    int e = blockIdx.x * blockDim.x + threadIdx.x;
    if (e >= E) return;
    int d = ei[E + e];
    int pos = atomicAdd(&g_cursor[d], 1);
    g_csrc[pos] = ei[e];
}

// ---------------- layer-2 attention logits ----------------
__global__ void node_attn2(const float* __restrict__ att_src, const float* __restrict__ att_dst, int Nn) {
    int i = blockIdx.x * blockDim.x + threadIdx.x;
    if (i >= Nn) return;
    const float* h = &g_h2[i * 40];
    float as = 0.f, ad = 0.f;
#pragma unroll
    for (int c = 0; c < 40; c++) {
        float v = h[c];
        as += v * att_src[c];
        ad += v * att_dst[c];
    }
    g_as2[i] = as;
    g_ad2[i] = ad;
}

// ---------------- Layer 1 aggregation: warp per node, zero barriers ----------------
// lane owns float2 channel pair (2*lane, 2*lane+1); head h = lane>>2.
// chunk = 4 edges; lane computes weight of (edge lane>>3, head lane&7); exchange via shfl.
__global__ void __launch_bounds__(256) agg1(const float* __restrict__ b1, int Nn) {
    int gw = (blockIdx.x * blockDim.x + threadIdx.x) >> 5;
    if (gw >= Nn) return;
    int i = gw;
    int lane = threadIdx.x & 31;
    int h = lane >> 2;
    const float2* h1f2 = (const float2*)g_h1;

    float adst_w = g_adst1[i * 8 + (lane & 7)];   // for weight computation role
    // self loop (my head)
    float wself = __expf(leaky(g_asrc1[i * 8 + h] + g_adst1[i * 8 + h]));
    float denom = wself;
    float2 hv0 = h1f2[i * 32 + lane];
    float2 acc = make_float2(wself * hv0.x, wself * hv0.y);

    int st = g_start[i], en = g_start[i + 1];
    for (int e0 = st; e0 < en; e0 += 4) {
        int idx = e0 + (lane >> 3);
        bool valid = idx < en;
        int s = valid ? g_csrc[idx] : 0;
        float w = valid ? __expf(leaky(g_asrc1[s * 8 + (lane & 7)] + adst_w)) : 0.f;
#pragma unroll
        for (int j = 0; j < 4; j++) {
            int sj = __shfl_sync(~0u, s, j * 8);
            float wj = __shfl_sync(~0u, w, j * 8 + h);
            float2 hv = h1f2[sj * 32 + lane];
            acc.x += wj * hv.x;
            acc.y += wj * hv.y;
            denom += wj;
        }
    }
    float inv = 1.f / (denom + 1e-16f);
    float2 bb = ((const float2*)b1)[lane];
    float vx = acc.x * inv + bb.x;
    float vy = acc.y * inv + bb.y;
    ((float2*)g_h2in)[i * 32 + lane] = make_float2(vx > 0.f ? vx : 0.f, vy > 0.f ? vy : 0.f);
}

// ---------------- Layer 2 aggregation: warp per node (H=1, C=40) ----------------
// lanes 0..19 own float2 channel pairs; chunk = 32 edges (1 per lane).
__global__ void __launch_bounds__(256) agg2(const float* __restrict__ b2,
                                            float* __restrict__ out, int Nn) {
    int gw = (blockIdx.x * blockDim.x + threadIdx.x) >> 5;
    if (gw >= Nn) return;
    int i = gw;
    int lane = threadIdx.x & 31;
    int cl = lane < 20 ? lane : 0;    // clamped channel index
    const float2* h2f2 = (const float2*)g_h2;

    float ad = g_ad2[i];
    float wself = __expf(leaky(g_as2[i] + ad));
    float denom = wself;
    float2 hv0 = h2f2[i * 20 + cl];
    float2 acc = make_float2(wself * hv0.x, wself * hv0.y);

    int st = g_start[i], en = g_start[i + 1];
    for (int e0 = st; e0 < en; e0 += 32) {
        int idx = e0 + lane;
        bool valid = idx < en;
        int s = valid ? g_csrc[idx] : 0;
        float w = valid ? __expf(leaky(g_as2[s] + ad)) : 0.f;
        int nleft = en - e0;
        int cnt = nleft < 32 ? nleft : 32;
#pragma unroll 8
        for (int j = 0; j < cnt; j++) {
            int sj = __shfl_sync(~0u, s, j);
            float wj = __shfl_sync(~0u, w, j);
            float2 hv = h2f2[sj * 20 + cl];
            acc.x += wj * hv.x;
            acc.y += wj * hv.y;
            denom += wj;
        }
    }
    float inv = 1.f / (denom + 1e-16f);
    float2 bb = ((const float2*)b2)[cl];
    float vx = acc.x * inv + bb.x;
    float vy = acc.y * inv + bb.y;

    // log_softmax across 40 values (lanes 0..19)
    float mloc = (lane < 20) ? fmaxf(vx, vy) : -1e30f;
#pragma unroll
    for (int o = 16; o > 0; o >>= 1) mloc = fmaxf(mloc, __shfl_xor_sync(~0u, mloc, o));
    float sloc = (lane < 20) ? (__expf(vx - mloc) + __expf(vy - mloc)) : 0.f;
#pragma unroll
    for (int o = 16; o > 0; o >>= 1) sloc += __shfl_xor_sync(~0u, sloc, o);
    float lse = mloc + logf(sloc);
    if (lane < 20)
        ((float2*)out)[i * 20 + lane] = make_float2(vx - lse, vy - lse);
}

// ---------------- launch ----------------
extern "C" void kernel_launch(void* const* d_in, const int* in_sizes, int n_in,
                              void* d_out, int out_size) {
    const float* x   = (const float*)d_in[0];
    const int*   ei  = (const int*)d_in[1];
    const float* W1  = (const float*)d_in[2];
    const float* as1 = (const float*)d_in[3];
    const float* ad1 = (const float*)d_in[4];
    const float* b1  = (const float*)d_in[5];
    const float* W2  = (const float*)d_in[6];
    const float* as2 = (const float*)d_in[7];
    const float* ad2 = (const float*)d_in[8];
    const float* b2  = (const float*)d_in[9];
    float* out = (float*)d_out;

    int Nn = in_sizes[0] / 512;   // 50000
    int E  = in_sizes[1] / 2;     // 1600000

    void *ph1, *ph2in, *ph2, *pdeg;
    cudaGetSymbolAddress(&ph1, g_h1);
    cudaGetSymbolAddress(&ph2in, g_h2in);
    cudaGetSymbolAddress(&ph2, g_h2);
    cudaGetSymbolAddress(&pdeg, g_deg);

    const int T = 256;
    int nChunks = (Nn + 1023) / 1024;
    int aggBlocks = (Nn + 7) / 8;   // 8 warps (nodes) per 256-thread block

    // CSR build (shared by both layers)
    cudaMemsetAsync(pdeg, 0, (size_t)Nn * sizeof(int));
    hist_dst<<<(E + T - 1) / T, T>>>(ei, E);
    scan_local<<<nChunks, 1024>>>(Nn);
    scan_spine<<<1, 32>>>(nChunks, Nn);
    scan_add<<<(Nn + T - 1) / T, T>>>(Nn);
    scatter_csr<<<(E + T - 1) / T, T>>>(ei, E);

    // layer 1 (attn logits fused into GEMM epilogue)
    sgemm1k<<<(Nn + 127) / 128, 128>>>(x, W1, (float*)ph1, as1, ad1, Nn);
    agg1<<<aggBlocks, T>>>(b1, Nn);

    // layer 2
    sgemm64<<<(Nn + 63) / 64, T>>>((const float*)ph2in, W2, (float*)ph2, Nn, 40, 64);
    node_attn2<<<(Nn + T - 1) / T, T>>>(as2, ad2, Nn);
    agg2<<<aggBlocks, T>>>(b2, out, Nn);
}